// round 4
// baseline (speedup 1.0000x reference)
#include <cuda_runtime.h>
#include <math.h>

#define D 4096
#define D4 1024
#define MAXR 16384
#define EPSF 1e-5f
#define EPS_VARF 1e-4f

// ---------------- device scratch (static; no allocations) ----------------
__device__ __align__(16) float  g_mean_in[D];
__device__ __align__(16) float  g_inv_in[D];
__device__ __align__(16) float  g_mean_out[D];
__device__ __align__(16) float  g_inv_out[D];
__device__ __align__(16) float  g_eman[D];
__device__ __align__(16) float  g_mask[D];
__device__ __align__(16) double g_novel[D];
__device__ __align__(16) float  g_rows2[MAXR];
__device__ __align__(16) float  g_rowsd[MAXR];
__device__ __align__(16) float  g_gc[MAXR];
__device__ float g_scal[6]; // tau, beta_up, beta_dn, gamma, beta_out, gamma_out

// ---------------- fast math helpers ----------------
__device__ __forceinline__ float tanh_fast(float x) {
    float y;
    asm("tanh.approx.f32 %0, %1;" : "=f"(y) : "f"(x));
    return y;
}

__device__ __forceinline__ float gelu_f(float x) {
    float x3 = x * x * x;
    float t  = tanh_fast(0.7978845608028654f * (x + 0.044715f * x3));
    return 0.5f * x * (1.0f + t);
}

// ---------------- prep: channel constants, scalars, zero accumulators ----------------
__global__ void prep_kernel(const float* __restrict__ ema_mean,
                            const float* __restrict__ ema_sq,
                            const float* __restrict__ ema_out_mean,
                            const float* __restrict__ ema_out_sq,
                            const float* __restrict__ ema_out_dir,
                            const float* __restrict__ log_tau,
                            const float* __restrict__ log_beta_up,
                            const float* __restrict__ log_beta_dn,
                            const float* __restrict__ log_gamma,
                            const float* __restrict__ log_beta_out,
                            const float* __restrict__ log_gamma_out)
{
    __shared__ float red[8];
    __shared__ float s_invn;
    int t = threadIdx.x; // 256 threads

    float s = 0.f;
    for (int c = t; c < D; c += 256) { float v = ema_out_dir[c]; s += v * v; }
    #pragma unroll
    for (int o = 16; o > 0; o >>= 1) s += __shfl_xor_sync(0xffffffffu, s, o);
    if ((t & 31) == 0) red[t >> 5] = s;
    __syncthreads();
    if (t == 0) {
        float tot = 0.f;
        #pragma unroll
        for (int i = 0; i < 8; i++) tot += red[i];
        s_invn = 1.0f / fmaxf(sqrtf(tot), 1e-12f);
        g_scal[0] = expf(log_tau[0]);
        g_scal[1] = log1pf(expf(log_beta_up[0]));
        g_scal[2] = log1pf(expf(log_beta_dn[0]));
        g_scal[3] = log1pf(expf(log_gamma[0]));
        g_scal[4] = log1pf(expf(log_beta_out[0]));
        g_scal[5] = log1pf(expf(log_gamma_out[0]));
    }
    __syncthreads();
    float invn = s_invn;

    for (int c = t; c < D; c += 256) {
        float m   = ema_mean[c];
        float var = fmaxf(ema_sq[c] - m * m, EPS_VARF);
        g_mean_in[c] = m;
        g_inv_in[c]  = 1.0f / (sqrtf(var) + EPSF);
        float mo   = ema_out_mean[c];
        float varo = fmaxf(ema_out_sq[c] - mo * mo, EPS_VARF);
        g_mean_out[c] = mo;
        g_inv_out[c]  = 1.0f / (sqrtf(varo) + EPSF);
        g_eman[c]  = ema_out_dir[c] * invn;
        g_novel[c] = 0.0;
    }
    for (int i = t; i < MAXR; i += 256) { g_rows2[i] = 0.f; g_rowsd[i] = 0.f; }
}

// ---------------- pass 1: per-channel novelty sums + per-row norm/dot partials ----------------
// grid: (4, rows/64), block: 256. Thread owns one float4 column group across 64 rows.
__global__ void __launch_bounds__(256) pass1_kernel(const float4* __restrict__ x4, int rows)
{
    __shared__ float srow2[64], srowd[64];
    int t = threadIdx.x;
    for (int i = t; i < 64; i += 256) { srow2[i] = 0.f; srowd[i] = 0.f; }
    __syncthreads();

    int c4 = blockIdx.x * 256 + t;
    int r0 = blockIdx.y * 64;
    if (r0 >= rows) return;
    int nr = rows - r0; if (nr > 64) nr = 64;
    int lane = t & 31;

    const float4 m  = *(const float4*)&g_mean_in[c4 * 4];
    const float4 iv = *(const float4*)&g_inv_in[c4 * 4];
    const float4 ea = *(const float4*)&g_eman[c4 * 4];

    double a0 = 0.0, a1 = 0.0, a2 = 0.0, a3 = 0.0;
    const float4* p = x4 + (size_t)r0 * D4 + c4;

    int rb = 0;
    for (; rb + 8 <= nr; rb += 8) {
        float p0 = 0.f, p1 = 0.f, p2 = 0.f, p3 = 0.f;
        #pragma unroll
        for (int i = 0; i < 8; i++) {
            float4 v = p[(size_t)(rb + i) * D4];
            p0 += fabsf(v.x - m.x) * iv.x;
            p1 += fabsf(v.y - m.y) * iv.y;
            p2 += fabsf(v.z - m.z) * iv.z;
            p3 += fabsf(v.w - m.w) * iv.w;
            float ox = gelu_f(v.x), oy = gelu_f(v.y), oz = gelu_f(v.z), ow = gelu_f(v.w);
            float s2 = ox * ox + oy * oy + oz * oz + ow * ow;
            float sd = ox * ea.x + oy * ea.y + oz * ea.z + ow * ea.w;
            #pragma unroll
            for (int o = 16; o > 0; o >>= 1) {
                s2 += __shfl_xor_sync(0xffffffffu, s2, o);
                sd += __shfl_xor_sync(0xffffffffu, sd, o);
            }
            if (lane == 0) {
                atomicAdd(&srow2[rb + i], s2);
                atomicAdd(&srowd[rb + i], sd);
            }
        }
        a0 += (double)p0; a1 += (double)p1; a2 += (double)p2; a3 += (double)p3;
    }
    for (; rb < nr; rb++) {
        float4 v = p[(size_t)rb * D4];
        a0 += (double)(fabsf(v.x - m.x) * iv.x);
        a1 += (double)(fabsf(v.y - m.y) * iv.y);
        a2 += (double)(fabsf(v.z - m.z) * iv.z);
        a3 += (double)(fabsf(v.w - m.w) * iv.w);
        float ox = gelu_f(v.x), oy = gelu_f(v.y), oz = gelu_f(v.z), ow = gelu_f(v.w);
        float s2 = ox * ox + oy * oy + oz * oz + ow * ow;
        float sd = ox * ea.x + oy * ea.y + oz * ea.z + ow * ea.w;
        #pragma unroll
        for (int o = 16; o > 0; o >>= 1) {
            s2 += __shfl_xor_sync(0xffffffffu, s2, o);
            sd += __shfl_xor_sync(0xffffffffu, sd, o);
        }
        if (lane == 0) { atomicAdd(&srow2[rb], s2); atomicAdd(&srowd[rb], sd); }
    }

    atomicAdd(&g_novel[c4 * 4 + 0], a0);
    atomicAdd(&g_novel[c4 * 4 + 1], a1);
    atomicAdd(&g_novel[c4 * 4 + 2], a2);
    atomicAdd(&g_novel[c4 * 4 + 3], a3);

    __syncthreads();
    for (int i = t; i < nr; i += 256) {
        atomicAdd(&g_rows2[r0 + i], srow2[i]);
        atomicAdd(&g_rowsd[r0 + i], srowd[i]);
    }
}

// ---------------- top-k hard mask (exact rank) + per-row gate_cos finalize ----------------
// grid: 256 blocks x 512 threads. One warp per channel; ballot-count over smem.
__global__ void __launch_bounds__(512) mask_kernel(const int* __restrict__ kptr, int rows)
{
    __shared__ double s[D];
    int t = threadIdx.x;
    for (int c = t; c < D; c += 512) s[c] = g_novel[c];

    // per-row gate_cos (first 16 blocks cover 8192 rows)
    int rowid = blockIdx.x * 512 + t;
    if (rowid < rows) {
        float s2v = g_rows2[rowid];
        float sdv = g_rowsd[rowid];
        float nrm = fmaxf(sqrtf(s2v), 1e-12f);
        float cs  = fminf(fmaxf(sdv / nrm, -1.0f), 1.0f);
        g_gc[rowid] = expf(-g_scal[0] * cs);
    }
    __syncthreads();

    int k = kptr[0];
    if (k < 1 || k > D) {
        float kf = __int_as_float(k);
        if (kf >= 1.0f && kf <= (float)D) k = (int)kf;
        else if (k < 1) k = 1;
        else k = D;
    }

    int w = t >> 5, lane = t & 31;
    int d = blockIdx.x * 16 + w;       // 256*16 = 4096 channels
    double sd = s[d];
    int cnt = 0;
    #pragma unroll 4
    for (int jj = 0; jj < D / 32; jj++) {
        int j = jj * 32 + lane;
        double v = s[j];
        bool p = (v > sd) || (v == sd && j < d);
        cnt += __popc(__ballot_sync(0xffffffffu, p));
    }
    if (lane == 0) g_mask[d] = (cnt < k) ? 1.0f : 0.0f;
}

// ---------------- pass 2: pure-streaming apply ----------------
__device__ __forceinline__ float apply_one(float x, float o,
                                           float mi, float ii, float mo, float io,
                                           float mk, float gc,
                                           float bu, float bd, float gm,
                                           float bo, float go)
{
    float zi = (x - mi) * ii;
    float zo = (o - mo) * io;
    float ti = tanh_fast(gm * zi);
    float gin = 1.0f + bu * fmaxf(ti, 0.0f) + bd * fminf(ti, 0.0f);
    gin = fminf(fmaxf(gin, 0.05f), 8.0f);
    float gout = 1.0f + bo * tanh_fast(go * zo);
    gout = fminf(fmaxf(gout, 0.1f), 5.0f);
    float g = gin * gout * gc;
    return o * (1.0f + mk * (g - 1.0f));
}

// block: 512 threads; each thread owns TWO float4 column groups (t and t+512),
// covering one full row per iteration. Channel constants register-resident
// across all rpb rows. Barrier-free pure stream.
__global__ void __launch_bounds__(512) apply2_kernel(const float4* __restrict__ x4,
                                                     float4* __restrict__ y4,
                                                     int rows, int rpb)
{
    int t = threadIdx.x;
    const float4 miA = *(const float4*)&g_mean_in[t * 4];
    const float4 iiA = *(const float4*)&g_inv_in[t * 4];
    const float4 moA = *(const float4*)&g_mean_out[t * 4];
    const float4 ioA = *(const float4*)&g_inv_out[t * 4];
    const float4 mkA = *(const float4*)&g_mask[t * 4];
    const float4 miB = *(const float4*)&g_mean_in[(t + 512) * 4];
    const float4 iiB = *(const float4*)&g_inv_in[(t + 512) * 4];
    const float4 moB = *(const float4*)&g_mean_out[(t + 512) * 4];
    const float4 ioB = *(const float4*)&g_inv_out[(t + 512) * 4];
    const float4 mkB = *(const float4*)&g_mask[(t + 512) * 4];
    const float bu = g_scal[1], bd = g_scal[2], gm = g_scal[3];
    const float bo = g_scal[4], go = g_scal[5];

    int r0 = blockIdx.x * rpb;
    int r1 = r0 + rpb; if (r1 > rows) r1 = rows;

    for (int r = r0; r < r1; r++) {
        float gc = g_gc[r];
        const float4* xp = x4 + (size_t)r * D4;
        float4* yp = y4 + (size_t)r * D4;

        float4 va = xp[t];
        float4 vb = xp[t + 512];

        float4 oa, ob;
        oa.x = gelu_f(va.x); oa.y = gelu_f(va.y); oa.z = gelu_f(va.z); oa.w = gelu_f(va.w);
        ob.x = gelu_f(vb.x); ob.y = gelu_f(vb.y); ob.z = gelu_f(vb.z); ob.w = gelu_f(vb.w);

        float4 ra;
        ra.x = apply_one(va.x, oa.x, miA.x, iiA.x, moA.x, ioA.x, mkA.x, gc, bu, bd, gm, bo, go);
        ra.y = apply_one(va.y, oa.y, miA.y, iiA.y, moA.y, ioA.y, mkA.y, gc, bu, bd, gm, bo, go);
        ra.z = apply_one(va.z, oa.z, miA.z, iiA.z, moA.z, ioA.z, mkA.z, gc, bu, bd, gm, bo, go);
        ra.w = apply_one(va.w, oa.w, miA.w, iiA.w, moA.w, ioA.w, mkA.w, gc, bu, bd, gm, bo, go);
        yp[t] = ra;

        float4 rb;
        rb.x = apply_one(vb.x, ob.x, miB.x, iiB.x, moB.x, ioB.x, mkB.x, gc, bu, bd, gm, bo, go);
        rb.y = apply_one(vb.y, ob.y, miB.y, iiB.y, moB.y, ioB.y, mkB.y, gc, bu, bd, gm, bo, go);
        rb.z = apply_one(vb.z, ob.z, miB.z, iiB.z, moB.z, ioB.z, mkB.z, gc, bu, bd, gm, bo, go);
        rb.w = apply_one(vb.w, ob.w, miB.w, iiB.w, moB.w, ioB.w, mkB.w, gc, bu, bd, gm, bo, go);
        yp[t + 512] = rb;
    }
}

// ---------------- launch ----------------
extern "C" void kernel_launch(void* const* d_in, const int* in_sizes, int n_in,
                              void* d_out, int out_size)
{
    (void)n_in; (void)out_size;
    const float* x             = (const float*)d_in[0];
    const float* log_tau       = (const float*)d_in[2];
    const float* log_beta_up   = (const float*)d_in[3];
    const float* log_beta_dn   = (const float*)d_in[4];
    const float* log_gamma     = (const float*)d_in[5];
    const float* log_beta_out  = (const float*)d_in[6];
    const float* log_gamma_out = (const float*)d_in[7];
    const float* ema_mean      = (const float*)d_in[9];
    const float* ema_sq        = (const float*)d_in[10];
    const float* ema_out_mean  = (const float*)d_in[11];
    const float* ema_out_sq    = (const float*)d_in[12];
    const float* ema_out_dir   = (const float*)d_in[13];
    const int*   kptr          = (const int*)d_in[14];

    int rows = in_sizes[0] / D; // 8192 for (4, 2048, 4096)

    prep_kernel<<<1, 256>>>(ema_mean, ema_sq, ema_out_mean, ema_out_sq, ema_out_dir,
                            log_tau, log_beta_up, log_beta_dn, log_gamma,
                            log_beta_out, log_gamma_out);

    dim3 ng(4, (rows + 63) / 64);
    pass1_kernel<<<ng, 256>>>((const float4*)x, rows);

    mask_kernel<<<256, 512>>>(kptr, rows);

    int rpb = 16;
    apply2_kernel<<<(rows + rpb - 1) / rpb, 512>>>((const float4*)x, (float4*)d_out, rows, rpb);
}

// round 5
// speedup vs baseline: 1.0700x; 1.0700x over previous
#include <cuda_runtime.h>
#include <math.h>

#define D 4096
#define D4 1024
#define MAXR 16384
#define EPSF 1e-5f
#define EPS_VARF 1e-4f

// ---------------- device scratch (static; no allocations) ----------------
__device__ __align__(16) float  g_mean_in[D];
__device__ __align__(16) float  g_inv_in[D];
__device__ __align__(16) float  g_mean_out[D];
__device__ __align__(16) float  g_inv_out[D];
__device__ __align__(16) float  g_eman[D];
__device__ __align__(16) float  g_mask[D];
__device__ __align__(16) double g_novel[D];
__device__ __align__(16) float  g_rows2[MAXR];
__device__ __align__(16) float  g_rowsd[MAXR];
__device__ __align__(16) float  g_gc[MAXR];
__device__ float g_scal[6]; // tau, beta_up, beta_dn, gamma, beta_out, gamma_out

// ---------------- fast math helpers ----------------
__device__ __forceinline__ float tanh_fast(float x) {
    float y;
    asm("tanh.approx.f32 %0, %1;" : "=f"(y) : "f"(x));
    return y;
}

__device__ __forceinline__ float gelu_f(float x) {
    float x3 = x * x * x;
    float t  = tanh_fast(0.7978845608028654f * (x + 0.044715f * x3));
    return 0.5f * x * (1.0f + t);
}

// ---------------- prep: channel constants, scalars, zero accumulators ----------------
__global__ void prep_kernel(const float* __restrict__ ema_mean,
                            const float* __restrict__ ema_sq,
                            const float* __restrict__ ema_out_mean,
                            const float* __restrict__ ema_out_sq,
                            const float* __restrict__ ema_out_dir,
                            const float* __restrict__ log_tau,
                            const float* __restrict__ log_beta_up,
                            const float* __restrict__ log_beta_dn,
                            const float* __restrict__ log_gamma,
                            const float* __restrict__ log_beta_out,
                            const float* __restrict__ log_gamma_out)
{
    __shared__ float red[8];
    __shared__ float s_invn;
    int t = threadIdx.x; // 256 threads

    float s = 0.f;
    for (int c = t; c < D; c += 256) { float v = ema_out_dir[c]; s += v * v; }
    #pragma unroll
    for (int o = 16; o > 0; o >>= 1) s += __shfl_xor_sync(0xffffffffu, s, o);
    if ((t & 31) == 0) red[t >> 5] = s;
    __syncthreads();
    if (t == 0) {
        float tot = 0.f;
        #pragma unroll
        for (int i = 0; i < 8; i++) tot += red[i];
        s_invn = 1.0f / fmaxf(sqrtf(tot), 1e-12f);
        g_scal[0] = expf(log_tau[0]);
        g_scal[1] = log1pf(expf(log_beta_up[0]));
        g_scal[2] = log1pf(expf(log_beta_dn[0]));
        g_scal[3] = log1pf(expf(log_gamma[0]));
        g_scal[4] = log1pf(expf(log_beta_out[0]));
        g_scal[5] = log1pf(expf(log_gamma_out[0]));
    }
    __syncthreads();
    float invn = s_invn;

    for (int c = t; c < D; c += 256) {
        float m   = ema_mean[c];
        float var = fmaxf(ema_sq[c] - m * m, EPS_VARF);
        g_mean_in[c] = m;
        g_inv_in[c]  = 1.0f / (sqrtf(var) + EPSF);
        float mo   = ema_out_mean[c];
        float varo = fmaxf(ema_out_sq[c] - mo * mo, EPS_VARF);
        g_mean_out[c] = mo;
        g_inv_out[c]  = 1.0f / (sqrtf(varo) + EPSF);
        g_eman[c]  = ema_out_dir[c] * invn;
        g_novel[c] = 0.0;
    }
    for (int i = t; i < MAXR; i += 256) { g_rows2[i] = 0.f; g_rowsd[i] = 0.f; }
}

// ---------------- pass 1: per-channel novelty (fp64) + per-row norm/dot ----------------
// grid: (4, rows/64), block: 256. Thread owns one float4 column group across 64 rows.
// Row partials: per 8-row tile, dump per-thread fp32 partials to smem, then
// warp w reduces row w (8 LDS + 5 SHFL), one global atomic per row per block.
__global__ void __launch_bounds__(256) pass1_kernel(const float4* __restrict__ x4, int rows)
{
    __shared__ float sh2[8][256];
    __shared__ float shd[8][256];
    int t = threadIdx.x;
    int w = t >> 5, lane = t & 31;

    int c4 = blockIdx.x * 256 + t;
    int r0 = blockIdx.y * 64;
    int nr = rows - r0; if (nr > 64) nr = 64;   // 64 for the bench shape

    const float4 m  = *(const float4*)&g_mean_in[c4 * 4];
    const float4 iv = *(const float4*)&g_inv_in[c4 * 4];
    const float4 ea = *(const float4*)&g_eman[c4 * 4];

    double a0 = 0.0, a1 = 0.0, a2 = 0.0, a3 = 0.0;
    const float4* p = x4 + (size_t)r0 * D4 + c4;

    for (int tile = 0; tile < 8; tile++) {
        int rb = tile * 8;
        float p0 = 0.f, p1 = 0.f, p2 = 0.f, p3 = 0.f;
        #pragma unroll
        for (int i = 0; i < 8; i++) {
            int rr = rb + i;
            float4 v;
            if (rr < nr) v = p[(size_t)rr * D4];
            else { v.x = m.x; v.y = m.y; v.z = m.z; v.w = m.w; } // zero z + zero gelu? no: gives z=0 but gelu(m)!=0
            // novelty partial (z contribution is 0 for padded rows)
            p0 += fabsf(v.x - m.x) * iv.x;
            p1 += fabsf(v.y - m.y) * iv.y;
            p2 += fabsf(v.z - m.z) * iv.z;
            p3 += fabsf(v.w - m.w) * iv.w;
            float ox = gelu_f(v.x), oy = gelu_f(v.y), oz = gelu_f(v.z), ow = gelu_f(v.w);
            float s2 = ox * ox + oy * oy + oz * oz + ow * ow;
            float sd = ox * ea.x + oy * ea.y + oz * ea.z + ow * ea.w;
            sh2[i][t] = s2;
            shd[i][t] = sd;
        }
        a0 += (double)p0; a1 += (double)p1; a2 += (double)p2; a3 += (double)p3;

        __syncthreads();
        // warp w reduces row (rb + w)
        float v2 = 0.f, vd = 0.f;
        #pragma unroll
        for (int j = 0; j < 8; j++) {
            v2 += sh2[w][lane + 32 * j];
            vd += shd[w][lane + 32 * j];
        }
        #pragma unroll
        for (int o = 16; o > 0; o >>= 1) {
            v2 += __shfl_xor_sync(0xffffffffu, v2, o);
            vd += __shfl_xor_sync(0xffffffffu, vd, o);
        }
        int rowg = rb + w;
        if (lane == 0 && rowg < nr) {
            atomicAdd(&g_rows2[r0 + rowg], v2);
            atomicAdd(&g_rowsd[r0 + rowg], vd);
        }
        __syncthreads();
    }

    atomicAdd(&g_novel[c4 * 4 + 0], a0);
    atomicAdd(&g_novel[c4 * 4 + 1], a1);
    atomicAdd(&g_novel[c4 * 4 + 2], a2);
    atomicAdd(&g_novel[c4 * 4 + 3], a3);
}

// ---------------- top-k hard mask (exact rank, int64 keys) + gate_cos finalize ----------------
// Positive doubles order identically as their int64 bit patterns -> ALU-pipe compares.
__global__ void __launch_bounds__(512) mask_kernel(const int* __restrict__ kptr, int rows)
{
    __shared__ long long s[D];
    int t = threadIdx.x;
    for (int c = t; c < D; c += 512) s[c] = __double_as_longlong(g_novel[c]);

    // per-row gate_cos (first 16 blocks cover 8192 rows)
    int rowid = blockIdx.x * 512 + t;
    if (rowid < rows) {
        float s2v = g_rows2[rowid];
        float sdv = g_rowsd[rowid];
        float nrm = fmaxf(sqrtf(s2v), 1e-12f);
        float cs  = fminf(fmaxf(sdv / nrm, -1.0f), 1.0f);
        g_gc[rowid] = expf(-g_scal[0] * cs);
    }
    __syncthreads();

    int k = kptr[0];
    if (k < 1 || k > D) {
        float kf = __int_as_float(k);
        if (kf >= 1.0f && kf <= (float)D) k = (int)kf;
        else if (k < 1) k = 1;
        else k = D;
    }

    int w = t >> 5, lane = t & 31;
    int d = blockIdx.x * 16 + w;       // 256*16 = 4096 channels
    long long sd = s[d];
    int cnt = 0;
    #pragma unroll 4
    for (int jj = 0; jj < D / 32; jj++) {
        int j = jj * 32 + lane;
        long long v = s[j];
        bool p = (v > sd) || (v == sd && j < d);
        cnt += __popc(__ballot_sync(0xffffffffu, p));
    }
    if (lane == 0) g_mask[d] = (cnt < k) ? 1.0f : 0.0f;
}

// ---------------- pass 2: pure-streaming apply ----------------
__device__ __forceinline__ float apply_one(float x, float o,
                                           float mi, float ii, float mo, float io,
                                           float mk, float gc,
                                           float bu, float bd, float gm,
                                           float bo, float go)
{
    float zi = (x - mi) * ii;
    float zo = (o - mo) * io;
    float ti = tanh_fast(gm * zi);
    float gin = 1.0f + bu * fmaxf(ti, 0.0f) + bd * fminf(ti, 0.0f);
    gin = fminf(fmaxf(gin, 0.05f), 8.0f);
    float gout = 1.0f + bo * tanh_fast(go * zo);
    gout = fminf(fmaxf(gout, 0.1f), 5.0f);
    float g = gin * gout * gc;
    return o * (1.0f + mk * (g - 1.0f));
}

__device__ __forceinline__ float4 apply_vec(float4 v, float gc,
                                            const float4& mi, const float4& ii,
                                            const float4& mo, const float4& io,
                                            const float4& mk,
                                            float bu, float bd, float gm,
                                            float bo, float go)
{
    float4 o;
    o.x = gelu_f(v.x); o.y = gelu_f(v.y); o.z = gelu_f(v.z); o.w = gelu_f(v.w);
    float4 r;
    r.x = apply_one(v.x, o.x, mi.x, ii.x, mo.x, io.x, mk.x, gc, bu, bd, gm, bo, go);
    r.y = apply_one(v.y, o.y, mi.y, ii.y, mo.y, io.y, mk.y, gc, bu, bd, gm, bo, go);
    r.z = apply_one(v.z, o.z, mi.z, ii.z, mo.z, io.z, mk.z, gc, bu, bd, gm, bo, go);
    r.w = apply_one(v.w, o.w, mi.w, ii.w, mo.w, io.w, mk.w, gc, bu, bd, gm, bo, go);
    return r;
}

// grid (4, rows/rpb), block 256. Thread owns ONE float4 column group (20 const
// regs), loops rpb rows, 2-row explicit unroll for MLP. No barriers, no smem.
__global__ void __launch_bounds__(256) apply2_kernel(const float4* __restrict__ x4,
                                                     float4* __restrict__ y4,
                                                     int rows, int rpb)
{
    int t = threadIdx.x;
    int c4 = blockIdx.x * 256 + t;
    const float4 mi = *(const float4*)&g_mean_in[c4 * 4];
    const float4 ii = *(const float4*)&g_inv_in[c4 * 4];
    const float4 mo = *(const float4*)&g_mean_out[c4 * 4];
    const float4 io = *(const float4*)&g_inv_out[c4 * 4];
    const float4 mk = *(const float4*)&g_mask[c4 * 4];
    const float bu = g_scal[1], bd = g_scal[2], gm = g_scal[3];
    const float bo = g_scal[4], go = g_scal[5];

    int r0 = blockIdx.y * rpb;
    int r1 = r0 + rpb; if (r1 > rows) r1 = rows;

    const float4* xp = x4 + c4;
    float4* yp = y4 + c4;

    int r = r0;
    for (; r + 2 <= r1; r += 2) {
        float gc0 = g_gc[r];
        float gc1 = g_gc[r + 1];
        float4 v0 = xp[(size_t)r * D4];
        float4 v1 = xp[(size_t)(r + 1) * D4];
        float4 o0 = apply_vec(v0, gc0, mi, ii, mo, io, mk, bu, bd, gm, bo, go);
        float4 o1 = apply_vec(v1, gc1, mi, ii, mo, io, mk, bu, bd, gm, bo, go);
        yp[(size_t)r * D4] = o0;
        yp[(size_t)(r + 1) * D4] = o1;
    }
    if (r < r1) {
        float gc0 = g_gc[r];
        float4 v0 = xp[(size_t)r * D4];
        yp[(size_t)r * D4] = apply_vec(v0, gc0, mi, ii, mo, io, mk, bu, bd, gm, bo, go);
    }
}

// ---------------- launch ----------------
extern "C" void kernel_launch(void* const* d_in, const int* in_sizes, int n_in,
                              void* d_out, int out_size)
{
    (void)n_in; (void)out_size;
    const float* x             = (const float*)d_in[0];
    const float* log_tau       = (const float*)d_in[2];
    const float* log_beta_up   = (const float*)d_in[3];
    const float* log_beta_dn   = (const float*)d_in[4];
    const float* log_gamma     = (const float*)d_in[5];
    const float* log_beta_out  = (const float*)d_in[6];
    const float* log_gamma_out = (const float*)d_in[7];
    const float* ema_mean      = (const float*)d_in[9];
    const float* ema_sq        = (const float*)d_in[10];
    const float* ema_out_mean  = (const float*)d_in[11];
    const float* ema_out_sq    = (const float*)d_in[12];
    const float* ema_out_dir   = (const float*)d_in[13];
    const int*   kptr          = (const int*)d_in[14];

    int rows = in_sizes[0] / D; // 8192 for (4, 2048, 4096)

    prep_kernel<<<1, 256>>>(ema_mean, ema_sq, ema_out_mean, ema_out_sq, ema_out_dir,
                            log_tau, log_beta_up, log_beta_dn, log_gamma,
                            log_beta_out, log_gamma_out);

    dim3 ng(4, (rows + 63) / 64);
    pass1_kernel<<<ng, 256>>>((const float4*)x, rows);

    mask_kernel<<<256, 512>>>(kptr, rows);

    int rpb = 16;
    dim3 ag(4, (rows + rpb - 1) / rpb);
    apply2_kernel<<<ag, 256>>>((const float4*)x, (float4*)d_out, rows, rpb);
}

// round 6
// speedup vs baseline: 1.2156x; 1.1361x over previous
#include <cuda_runtime.h>
#include <math.h>

#define D 4096
#define D4 1024
#define MAXR 16384
#define EPSF 1e-5f
#define EPS_VARF 1e-4f

// ---------------- device scratch (static; no allocations) ----------------
// Folded per-channel affine constants: z = x*a + b
__device__ __align__(16) float  g_ain[D];    // 1/(sqrt(var_in)+eps)
__device__ __align__(16) float  g_bin[D];    // -mean_in * ain
__device__ __align__(16) float  g_aout[D];   // 1/(sqrt(var_out)+eps)
__device__ __align__(16) float  g_bout[D];   // -mean_out * aout
__device__ __align__(16) float  g_eman[D];   // normalized ema_out_dir
__device__ __align__(16) float  g_mask[D];
__device__ __align__(16) double g_novel[D];
__device__ __align__(16) float  g_rows2[MAXR];
__device__ __align__(16) float  g_rowsd[MAXR];
__device__ __align__(16) float  g_gc[MAXR];
__device__ float g_scal[6]; // tau, A=(bu+bd)/2, B=(bu-bd)/2, gamma, beta_out, gamma_out

// ---------------- fast math helpers ----------------
__device__ __forceinline__ float tanh_fast(float x) {
    float y;
    asm("tanh.approx.f32 %0, %1;" : "=f"(y) : "f"(x));
    return y;
}

__device__ __forceinline__ float gelu_f(float x) {
    float x2 = x * x;
    // c*(x + 0.044715 x^3) = x*(c + c*0.044715*x^2)
    float arg = x * fmaf(0.035677408136300125f, x2, 0.7978845608028654f);
    float t = tanh_fast(arg);
    float h = 0.5f * x;
    return fmaf(h, t, h);
}

// ---------------- prep: folded channel constants, scalars, zero accumulators ----------------
__global__ void prep_kernel(const float* __restrict__ ema_mean,
                            const float* __restrict__ ema_sq,
                            const float* __restrict__ ema_out_mean,
                            const float* __restrict__ ema_out_sq,
                            const float* __restrict__ ema_out_dir,
                            const float* __restrict__ log_tau,
                            const float* __restrict__ log_beta_up,
                            const float* __restrict__ log_beta_dn,
                            const float* __restrict__ log_gamma,
                            const float* __restrict__ log_beta_out,
                            const float* __restrict__ log_gamma_out)
{
    __shared__ float red[8];
    __shared__ float s_invn;
    int t = threadIdx.x; // 256 threads

    float s = 0.f;
    for (int c = t; c < D; c += 256) { float v = ema_out_dir[c]; s += v * v; }
    #pragma unroll
    for (int o = 16; o > 0; o >>= 1) s += __shfl_xor_sync(0xffffffffu, s, o);
    if ((t & 31) == 0) red[t >> 5] = s;
    __syncthreads();
    if (t == 0) {
        float tot = 0.f;
        #pragma unroll
        for (int i = 0; i < 8; i++) tot += red[i];
        s_invn = 1.0f / fmaxf(sqrtf(tot), 1e-12f);
        float bu = log1pf(expf(log_beta_up[0]));
        float bd = log1pf(expf(log_beta_dn[0]));
        g_scal[0] = expf(log_tau[0]);
        g_scal[1] = 0.5f * (bu + bd);            // A
        g_scal[2] = 0.5f * (bu - bd);            // B
        g_scal[3] = log1pf(expf(log_gamma[0]));  // gamma
        g_scal[4] = log1pf(expf(log_beta_out[0]));
        g_scal[5] = log1pf(expf(log_gamma_out[0]));
    }
    __syncthreads();
    float invn = s_invn;

    for (int c = t; c < D; c += 256) {
        float m   = ema_mean[c];
        float var = fmaxf(ema_sq[c] - m * m, EPS_VARF);
        float ai  = 1.0f / (sqrtf(var) + EPSF);
        g_ain[c] = ai;
        g_bin[c] = -m * ai;
        float mo   = ema_out_mean[c];
        float varo = fmaxf(ema_out_sq[c] - mo * mo, EPS_VARF);
        float ao   = 1.0f / (sqrtf(varo) + EPSF);
        g_aout[c] = ao;
        g_bout[c] = -mo * ao;
        g_eman[c]  = ema_out_dir[c] * invn;
        g_novel[c] = 0.0;
    }
    for (int i = t; i < MAXR; i += 256) { g_rows2[i] = 0.f; g_rowsd[i] = 0.f; }
}

// ---------------- pass 1: per-channel novelty (fp64) + per-row norm/dot ----------------
// grid: (4, rows/64), block: 256. Thread owns one float4 column group across 64 rows.
// Barrier-free: row sums via 10 warp shuffles/row + 1-lane REDG to distinct addresses.
__global__ void __launch_bounds__(256) pass1_kernel(const float4* __restrict__ x4, int rows)
{
    int t = threadIdx.x;
    int lane = t & 31;

    int c4 = blockIdx.x * 256 + t;
    int r0 = blockIdx.y * 64;

    const float4 ai = *(const float4*)&g_ain[c4 * 4];
    const float4 bi = *(const float4*)&g_bin[c4 * 4];
    const float4 ea = *(const float4*)&g_eman[c4 * 4];

    double a0 = 0.0, a1 = 0.0, a2 = 0.0, a3 = 0.0;
    const float4* p = x4 + (size_t)r0 * D4 + c4;

    if (r0 + 64 <= rows) {
        // fast path: full 64-row tile, 8-row load batches for MLP
        for (int tile = 0; tile < 8; tile++) {
            int rb = tile * 8;
            float4 v[8];
            #pragma unroll
            for (int i = 0; i < 8; i++) v[i] = p[(size_t)(rb + i) * D4];

            float p0 = 0.f, p1 = 0.f, p2 = 0.f, p3 = 0.f;
            #pragma unroll
            for (int i = 0; i < 8; i++) {
                float z0 = fmaf(v[i].x, ai.x, bi.x);
                float z1 = fmaf(v[i].y, ai.y, bi.y);
                float z2 = fmaf(v[i].z, ai.z, bi.z);
                float z3 = fmaf(v[i].w, ai.w, bi.w);
                p0 += fabsf(z0); p1 += fabsf(z1); p2 += fabsf(z2); p3 += fabsf(z3);
                float o0 = gelu_f(v[i].x), o1 = gelu_f(v[i].y);
                float o2 = gelu_f(v[i].z), o3 = gelu_f(v[i].w);
                float s2 = fmaf(o0, o0, fmaf(o1, o1, fmaf(o2, o2, o3 * o3)));
                float sd = fmaf(o0, ea.x, fmaf(o1, ea.y, fmaf(o2, ea.z, o3 * ea.w)));
                #pragma unroll
                for (int o = 16; o > 0; o >>= 1) {
                    s2 += __shfl_xor_sync(0xffffffffu, s2, o);
                    sd += __shfl_xor_sync(0xffffffffu, sd, o);
                }
                if (lane == 0) {
                    atomicAdd(&g_rows2[r0 + rb + i], s2);
                    atomicAdd(&g_rowsd[r0 + rb + i], sd);
                }
            }
            a0 += (double)p0; a1 += (double)p1; a2 += (double)p2; a3 += (double)p3;
        }
    } else {
        int nr = rows - r0; if (nr < 0) nr = 0;
        for (int r = 0; r < nr; r++) {
            float4 v = p[(size_t)r * D4];
            float z0 = fmaf(v.x, ai.x, bi.x);
            float z1 = fmaf(v.y, ai.y, bi.y);
            float z2 = fmaf(v.z, ai.z, bi.z);
            float z3 = fmaf(v.w, ai.w, bi.w);
            a0 += (double)fabsf(z0); a1 += (double)fabsf(z1);
            a2 += (double)fabsf(z2); a3 += (double)fabsf(z3);
            float o0 = gelu_f(v.x), o1 = gelu_f(v.y);
            float o2 = gelu_f(v.z), o3 = gelu_f(v.w);
            float s2 = fmaf(o0, o0, fmaf(o1, o1, fmaf(o2, o2, o3 * o3)));
            float sd = fmaf(o0, ea.x, fmaf(o1, ea.y, fmaf(o2, ea.z, o3 * ea.w)));
            #pragma unroll
            for (int o = 16; o > 0; o >>= 1) {
                s2 += __shfl_xor_sync(0xffffffffu, s2, o);
                sd += __shfl_xor_sync(0xffffffffu, sd, o);
            }
            if (lane == 0) {
                atomicAdd(&g_rows2[r0 + r], s2);
                atomicAdd(&g_rowsd[r0 + r], sd);
            }
        }
    }

    atomicAdd(&g_novel[c4 * 4 + 0], a0);
    atomicAdd(&g_novel[c4 * 4 + 1], a1);
    atomicAdd(&g_novel[c4 * 4 + 2], a2);
    atomicAdd(&g_novel[c4 * 4 + 3], a3);
}

// ---------------- top-k hard mask (exact rank, int64 keys) + gate_cos finalize ----------------
// Positive doubles order identically as their int64 bit patterns -> ALU-pipe compares.
__global__ void __launch_bounds__(512) mask_kernel(const int* __restrict__ kptr, int rows)
{
    __shared__ long long s[D];
    int t = threadIdx.x;
    for (int c = t; c < D; c += 512) s[c] = __double_as_longlong(g_novel[c]);

    int rowid = blockIdx.x * 512 + t;
    if (rowid < rows) {
        float s2v = g_rows2[rowid];
        float sdv = g_rowsd[rowid];
        float nrm = fmaxf(sqrtf(s2v), 1e-12f);
        float cs  = fminf(fmaxf(sdv / nrm, -1.0f), 1.0f);
        g_gc[rowid] = expf(-g_scal[0] * cs);
    }
    __syncthreads();

    int k = kptr[0];
    if (k < 1 || k > D) {
        float kf = __int_as_float(k);
        if (kf >= 1.0f && kf <= (float)D) k = (int)kf;
        else if (k < 1) k = 1;
        else k = D;
    }

    int w = t >> 5, lane = t & 31;
    int d = blockIdx.x * 16 + w;       // 256*16 = 4096 channels
    long long sd = s[d];
    int cnt = 0;
    #pragma unroll 4
    for (int jj = 0; jj < D / 32; jj++) {
        int j = jj * 32 + lane;
        long long v = s[j];
        bool p = (v > sd) || (v == sd && j < d);
        cnt += __popc(__ballot_sync(0xffffffffu, p));
    }
    if (lane == 0) g_mask[d] = (cnt < k) ? 1.0f : 0.0f;
}

// ---------------- pass 2: pure-streaming apply (instruction-dieted) ----------------
// Per element: o=gelu(x); t1=tanh(x*c1+c2); gin=clamp(1+A*t1+B*|t1|);
// t2=tanh(o*c3+c4); gout=clamp(1+bo*t2); y=o*(1+mk*(gin*gout*gc-1)).
__device__ __forceinline__ float apply_one(float x, float gc,
                                           float c1, float c2, float c3, float c4,
                                           float mk, float A, float B, float bo)
{
    float o = gelu_f(x);
    float t1 = tanh_fast(fmaf(x, c1, c2));
    float gin = fmaf(B, fabsf(t1), fmaf(A, t1, 1.0f));
    gin = fminf(fmaxf(gin, 0.05f), 8.0f);
    float t2 = tanh_fast(fmaf(o, c3, c4));
    float gout = fmaf(bo, t2, 1.0f);
    gout = fminf(fmaxf(gout, 0.1f), 5.0f);
    float g = gin * gout * gc;
    return o * fmaf(mk, g - 1.0f, 1.0f);
}

__device__ __forceinline__ float4 apply_vec(float4 v, float gc,
                                            const float4& c1, const float4& c2,
                                            const float4& c3, const float4& c4,
                                            const float4& mk,
                                            float A, float B, float bo)
{
    float4 r;
    r.x = apply_one(v.x, gc, c1.x, c2.x, c3.x, c4.x, mk.x, A, B, bo);
    r.y = apply_one(v.y, gc, c1.y, c2.y, c3.y, c4.y, mk.y, A, B, bo);
    r.z = apply_one(v.z, gc, c1.z, c2.z, c3.z, c4.z, mk.z, A, B, bo);
    r.w = apply_one(v.w, gc, c1.w, c2.w, c3.w, c4.w, mk.w, A, B, bo);
    return r;
}

// grid (4, rows/rpb), block 256. Thread owns ONE float4 column group; gamma
// factors folded into channel constants once per block. Barrier-free stream.
__global__ void __launch_bounds__(256) apply2_kernel(const float4* __restrict__ x4,
                                                     float4* __restrict__ y4,
                                                     int rows, int rpb)
{
    int t = threadIdx.x;
    int c4 = blockIdx.x * 256 + t;

    const float gm = g_scal[3], go = g_scal[5];
    const float A = g_scal[1], B = g_scal[2], bo = g_scal[4];

    float4 c1 = *(const float4*)&g_ain[c4 * 4];
    float4 c2 = *(const float4*)&g_bin[c4 * 4];
    float4 c3 = *(const float4*)&g_aout[c4 * 4];
    float4 c4v = *(const float4*)&g_bout[c4 * 4];
    const float4 mk = *(const float4*)&g_mask[c4 * 4];
    c1.x *= gm; c1.y *= gm; c1.z *= gm; c1.w *= gm;
    c2.x *= gm; c2.y *= gm; c2.z *= gm; c2.w *= gm;
    c3.x *= go; c3.y *= go; c3.z *= go; c3.w *= go;
    c4v.x *= go; c4v.y *= go; c4v.z *= go; c4v.w *= go;

    int r0 = blockIdx.y * rpb;
    int r1 = r0 + rpb; if (r1 > rows) r1 = rows;

    const float4* xp = x4 + c4;
    float4* yp = y4 + c4;

    int r = r0;
    for (; r + 2 <= r1; r += 2) {
        float gc0 = g_gc[r];
        float gc1 = g_gc[r + 1];
        float4 v0 = xp[(size_t)r * D4];
        float4 v1 = xp[(size_t)(r + 1) * D4];
        float4 o0 = apply_vec(v0, gc0, c1, c2, c3, c4v, mk, A, B, bo);
        float4 o1 = apply_vec(v1, gc1, c1, c2, c3, c4v, mk, A, B, bo);
        yp[(size_t)r * D4] = o0;
        yp[(size_t)(r + 1) * D4] = o1;
    }
    if (r < r1) {
        float gc0 = g_gc[r];
        float4 v0 = xp[(size_t)r * D4];
        yp[(size_t)r * D4] = apply_vec(v0, gc0, c1, c2, c3, c4v, mk, A, B, bo);
    }
}

// ---------------- launch ----------------
extern "C" void kernel_launch(void* const* d_in, const int* in_sizes, int n_in,
                              void* d_out, int out_size)
{
    (void)n_in; (void)out_size;
    const float* x             = (const float*)d_in[0];
    const float* log_tau       = (const float*)d_in[2];
    const float* log_beta_up   = (const float*)d_in[3];
    const float* log_beta_dn   = (const float*)d_in[4];
    const float* log_gamma     = (const float*)d_in[5];
    const float* log_beta_out  = (const float*)d_in[6];
    const float* log_gamma_out = (const float*)d_in[7];
    const float* ema_mean      = (const float*)d_in[9];
    const float* ema_sq        = (const float*)d_in[10];
    const float* ema_out_mean  = (const float*)d_in[11];
    const float* ema_out_sq    = (const float*)d_in[12];
    const float* ema_out_dir   = (const float*)d_in[13];
    const int*   kptr          = (const int*)d_in[14];

    int rows = in_sizes[0] / D; // 8192 for (4, 2048, 4096)

    prep_kernel<<<1, 256>>>(ema_mean, ema_sq, ema_out_mean, ema_out_sq, ema_out_dir,
                            log_tau, log_beta_up, log_beta_dn, log_gamma,
                            log_beta_out, log_gamma_out);

    dim3 ng(4, (rows + 63) / 64);
    pass1_kernel<<<ng, 256>>>((const float4*)x, rows);

    mask_kernel<<<256, 512>>>(kptr, rows);

    int rpb = 16;
    dim3 ag(4, (rows + rpb - 1) / rpb);
    apply2_kernel<<<ag, 256>>>((const float4*)x, (float4*)d_out, rows, rpb);
}

// round 8
// speedup vs baseline: 1.2741x; 1.0481x over previous
#include <cuda_runtime.h>
#include <math.h>

#define D 4096
#define D4 1024
#define MAXR 16384
#define EPSF 1e-5f
#define EPS_VARF 1e-4f

// ---------------- device scratch (static; no allocations) ----------------
__device__ __align__(16) float  g_ain[D];    // 1/(sqrt(var_in)+eps)
__device__ __align__(16) float  g_bin[D];    // -mean_in * ain
__device__ __align__(16) float  g_aout[D];   // 1/(sqrt(var_out)+eps)
__device__ __align__(16) float  g_bout[D];   // -mean_out * aout
__device__ __align__(16) float  g_eman[D];   // normalized ema_out_dir
__device__ __align__(16) float  g_mask[D];
__device__ __align__(16) double g_novel[D];
__device__ __align__(16) float  g_rows2[MAXR];
__device__ __align__(16) float  g_rowsd[MAXR];
__device__ __align__(16) float  g_gc[MAXR];
__device__ float g_scal[6]; // tau, A=(bu+bd)/2, B=(bu-bd)/2, gamma, beta_out, gamma_out

// ---------------- fast math helpers ----------------
__device__ __forceinline__ float tanh_fast(float x) {
    float y;
    asm("tanh.approx.f32 %0, %1;" : "=f"(y) : "f"(x));
    return y;
}

__device__ __forceinline__ float gelu_f(float x) {
    float x2 = x * x;
    float arg = x * fmaf(0.035677408136300125f, x2, 0.7978845608028654f);
    float t = tanh_fast(arg);
    float h = 0.5f * x;
    return fmaf(h, t, h);
}

// ---------------- prep: folded channel constants, scalars, zero accumulators ----------------
__global__ void prep_kernel(const float* __restrict__ ema_mean,
                            const float* __restrict__ ema_sq,
                            const float* __restrict__ ema_out_mean,
                            const float* __restrict__ ema_out_sq,
                            const float* __restrict__ ema_out_dir,
                            const float* __restrict__ log_tau,
                            const float* __restrict__ log_beta_up,
                            const float* __restrict__ log_beta_dn,
                            const float* __restrict__ log_gamma,
                            const float* __restrict__ log_beta_out,
                            const float* __restrict__ log_gamma_out)
{
    __shared__ float red[8];
    __shared__ float s_invn;
    int t = threadIdx.x; // 256 threads

    float s = 0.f;
    for (int c = t; c < D; c += 256) { float v = ema_out_dir[c]; s += v * v; }
    #pragma unroll
    for (int o = 16; o > 0; o >>= 1) s += __shfl_xor_sync(0xffffffffu, s, o);
    if ((t & 31) == 0) red[t >> 5] = s;
    __syncthreads();
    if (t == 0) {
        float tot = 0.f;
        #pragma unroll
        for (int i = 0; i < 8; i++) tot += red[i];
        s_invn = 1.0f / fmaxf(sqrtf(tot), 1e-12f);
        float bu = log1pf(expf(log_beta_up[0]));
        float bd = log1pf(expf(log_beta_dn[0]));
        g_scal[0] = expf(log_tau[0]);
        g_scal[1] = 0.5f * (bu + bd);            // A
        g_scal[2] = 0.5f * (bu - bd);            // B
        g_scal[3] = log1pf(expf(log_gamma[0]));  // gamma
        g_scal[4] = log1pf(expf(log_beta_out[0]));
        g_scal[5] = log1pf(expf(log_gamma_out[0]));
    }
    __syncthreads();
    float invn = s_invn;

    for (int c = t; c < D; c += 256) {
        float m   = ema_mean[c];
        float var = fmaxf(ema_sq[c] - m * m, EPS_VARF);
        float ai  = 1.0f / (sqrtf(var) + EPSF);
        g_ain[c] = ai;
        g_bin[c] = -m * ai;
        float mo   = ema_out_mean[c];
        float varo = fmaxf(ema_out_sq[c] - mo * mo, EPS_VARF);
        float ao   = 1.0f / (sqrtf(varo) + EPSF);
        g_aout[c] = ao;
        g_bout[c] = -mo * ao;
        g_eman[c]  = ema_out_dir[c] * invn;
        g_novel[c] = 0.0;
    }
    for (int i = t; i < MAXR; i += 256) { g_rows2[i] = 0.f; g_rowsd[i] = 0.f; }
}

// ---------------- pass 1: per-channel novelty (fp64) + per-row norm/dot ----------------
// grid: (4, rows/64), block: 256. Thread owns one float4 column group across 64 rows.
// Row sums: interleaved 5-step SHFL butterflies (two chains overlap), lane0 REDG.
__global__ void __launch_bounds__(256) pass1_kernel(const float4* __restrict__ x4, int rows)
{
    int t = threadIdx.x;
    int lane = t & 31;

    int c4 = blockIdx.x * 256 + t;
    int r0 = blockIdx.y * 64;

    const float4 ai = *(const float4*)&g_ain[c4 * 4];
    const float4 bi = *(const float4*)&g_bin[c4 * 4];
    const float4 ea = *(const float4*)&g_eman[c4 * 4];

    double a0 = 0.0, a1 = 0.0, a2 = 0.0, a3 = 0.0;
    const float4* p = x4 + (size_t)r0 * D4 + c4;

    if (r0 + 64 <= rows) {
        for (int tile = 0; tile < 8; tile++) {
            int rb = tile * 8;
            float4 v[8];
            #pragma unroll
            for (int i = 0; i < 8; i++) v[i] = p[(size_t)(rb + i) * D4];

            float p0 = 0.f, p1 = 0.f, p2 = 0.f, p3 = 0.f;
            #pragma unroll
            for (int i = 0; i < 8; i++) {
                float z0 = fmaf(v[i].x, ai.x, bi.x);
                float z1 = fmaf(v[i].y, ai.y, bi.y);
                float z2 = fmaf(v[i].z, ai.z, bi.z);
                float z3 = fmaf(v[i].w, ai.w, bi.w);
                p0 += fabsf(z0); p1 += fabsf(z1); p2 += fabsf(z2); p3 += fabsf(z3);
                float o0 = gelu_f(v[i].x), o1 = gelu_f(v[i].y);
                float o2 = gelu_f(v[i].z), o3 = gelu_f(v[i].w);
                float s2 = fmaf(o0, o0, fmaf(o1, o1, fmaf(o2, o2, o3 * o3)));
                float sd = fmaf(o0, ea.x, fmaf(o1, ea.y, fmaf(o2, ea.z, o3 * ea.w)));
                // interleaved butterflies: the two dependence chains overlap
                #pragma unroll
                for (int o = 16; o > 0; o >>= 1) {
                    float s2o = __shfl_xor_sync(0xffffffffu, s2, o);
                    float sdo = __shfl_xor_sync(0xffffffffu, sd, o);
                    s2 += s2o;
                    sd += sdo;
                }
                if (lane == 0) {
                    atomicAdd(&g_rows2[r0 + rb + i], s2);
                    atomicAdd(&g_rowsd[r0 + rb + i], sd);
                }
            }
            a0 += (double)p0; a1 += (double)p1; a2 += (double)p2; a3 += (double)p3;
        }
    } else {
        int nr = rows - r0; if (nr < 0) nr = 0;
        for (int r = 0; r < nr; r++) {
            float4 v = p[(size_t)r * D4];
            float z0 = fmaf(v.x, ai.x, bi.x);
            float z1 = fmaf(v.y, ai.y, bi.y);
            float z2 = fmaf(v.z, ai.z, bi.z);
            float z3 = fmaf(v.w, ai.w, bi.w);
            a0 += (double)fabsf(z0); a1 += (double)fabsf(z1);
            a2 += (double)fabsf(z2); a3 += (double)fabsf(z3);
            float o0 = gelu_f(v.x), o1 = gelu_f(v.y);
            float o2 = gelu_f(v.z), o3 = gelu_f(v.w);
            float s2 = fmaf(o0, o0, fmaf(o1, o1, fmaf(o2, o2, o3 * o3)));
            float sd = fmaf(o0, ea.x, fmaf(o1, ea.y, fmaf(o2, ea.z, o3 * ea.w)));
            #pragma unroll
            for (int o = 16; o > 0; o >>= 1) {
                float s2o = __shfl_xor_sync(0xffffffffu, s2, o);
                float sdo = __shfl_xor_sync(0xffffffffu, sd, o);
                s2 += s2o;
                sd += sdo;
            }
            if (lane == 0) {
                atomicAdd(&g_rows2[r0 + r], s2);
                atomicAdd(&g_rowsd[r0 + r], sd);
            }
        }
    }

    atomicAdd(&g_novel[c4 * 4 + 0], a0);
    atomicAdd(&g_novel[c4 * 4 + 1], a1);
    atomicAdd(&g_novel[c4 * 4 + 2], a2);
    atomicAdd(&g_novel[c4 * 4 + 3], a3);
}

// ---------------- top-k hard mask (exact rank, int64 keys) + gate_cos finalize ----------------
__global__ void __launch_bounds__(512) mask_kernel(const int* __restrict__ kptr, int rows)
{
    __shared__ long long s[D];
    int t = threadIdx.x;
    for (int c = t; c < D; c += 512) s[c] = __double_as_longlong(g_novel[c]);

    int rowid = blockIdx.x * 512 + t;
    if (rowid < rows) {
        float s2v = g_rows2[rowid];
        float sdv = g_rowsd[rowid];
        float nrm = fmaxf(sqrtf(s2v), 1e-12f);
        float cs  = fminf(fmaxf(sdv / nrm, -1.0f), 1.0f);
        g_gc[rowid] = expf(-g_scal[0] * cs);
    }
    __syncthreads();

    int k = kptr[0];
    if (k < 1 || k > D) {
        float kf = __int_as_float(k);
        if (kf >= 1.0f && kf <= (float)D) k = (int)kf;
        else if (k < 1) k = 1;
        else k = D;
    }

    int w = t >> 5, lane = t & 31;
    int d = blockIdx.x * 16 + w;       // 256*16 = 4096 channels
    long long sd = s[d];
    int cnt = 0;
    #pragma unroll 4
    for (int jj = 0; jj < D / 32; jj++) {
        int j = jj * 32 + lane;
        long long v = s[j];
        bool p = (v > sd) || (v == sd && j < d);
        cnt += __popc(__ballot_sync(0xffffffffu, p));
    }
    if (lane == 0) g_mask[d] = (cnt < k) ? 1.0f : 0.0f;
}

// ---------------- pass 2: streaming apply, reversed rows (L2-LIFO), 4-row unroll ----------------
__device__ __forceinline__ float apply_one(float x, float gc,
                                           float c1, float c2, float c3, float c4,
                                           float mk, float A, float B, float bo)
{
    float o = gelu_f(x);
    float t1 = tanh_fast(fmaf(x, c1, c2));
    float gin = fmaf(B, fabsf(t1), fmaf(A, t1, 1.0f));
    gin = fminf(fmaxf(gin, 0.05f), 8.0f);
    float t2 = tanh_fast(fmaf(o, c3, c4));
    float gout = fmaf(bo, t2, 1.0f);
    gout = fminf(fmaxf(gout, 0.1f), 5.0f);
    float g = gin * gout * gc;
    return o * fmaf(mk, g - 1.0f, 1.0f);
}

__device__ __forceinline__ float4 apply_vec(float4 v, float gc,
                                            const float4& c1, const float4& c2,
                                            const float4& c3, const float4& c4,
                                            const float4& mk,
                                            float A, float B, float bo)
{
    float4 r;
    r.x = apply_one(v.x, gc, c1.x, c2.x, c3.x, c4.x, mk.x, A, B, bo);
    r.y = apply_one(v.y, gc, c1.y, c2.y, c3.y, c4.y, mk.y, A, B, bo);
    r.z = apply_one(v.z, gc, c1.z, c2.z, c3.z, c4.z, mk.z, A, B, bo);
    r.w = apply_one(v.w, gc, c1.w, c2.w, c3.w, c4.w, mk.w, A, B, bo);
    return r;
}

// grid (4, ceil(rows/rpb)), block 256. Row blocks mapped in REVERSE so the first
// blocks touch the rows pass1 streamed last (still L2-resident); descending
// traversal is LIFO-optimal under LRU. Output stored with .cs (evict-first)
// to preserve x's L2 residency.
__global__ void __launch_bounds__(256) apply2_kernel(const float4* __restrict__ x4,
                                                     float4* __restrict__ y4,
                                                     int rows, int rpb)
{
    int t = threadIdx.x;
    int c4 = blockIdx.x * 256 + t;

    const float gm = g_scal[3], go = g_scal[5];
    const float A = g_scal[1], B = g_scal[2], bo = g_scal[4];

    float4 c1 = *(const float4*)&g_ain[c4 * 4];
    float4 c2 = *(const float4*)&g_bin[c4 * 4];
    float4 c3 = *(const float4*)&g_aout[c4 * 4];
    float4 c4v = *(const float4*)&g_bout[c4 * 4];
    const float4 mk = *(const float4*)&g_mask[c4 * 4];
    c1.x *= gm; c1.y *= gm; c1.z *= gm; c1.w *= gm;
    c2.x *= gm; c2.y *= gm; c2.z *= gm; c2.w *= gm;
    c3.x *= go; c3.y *= go; c3.z *= go; c3.w *= go;
    c4v.x *= go; c4v.y *= go; c4v.z *= go; c4v.w *= go;

    // reversed row range for this block
    int r_end = rows - blockIdx.y * rpb;
    int r_begin = r_end - rpb; if (r_begin < 0) r_begin = 0;

    const float4* xp = x4 + c4;
    float4* yp = y4 + c4;

    int r = r_begin;
    for (; r + 4 <= r_end; r += 4) {
        float gc0 = g_gc[r],     gc1 = g_gc[r + 1];
        float gc2 = g_gc[r + 2], gc3 = g_gc[r + 3];
        float4 v0 = xp[(size_t)r * D4];
        float4 v1 = xp[(size_t)(r + 1) * D4];
        float4 v2 = xp[(size_t)(r + 2) * D4];
        float4 v3 = xp[(size_t)(r + 3) * D4];
        float4 o0 = apply_vec(v0, gc0, c1, c2, c3, c4v, mk, A, B, bo);
        float4 o1 = apply_vec(v1, gc1, c1, c2, c3, c4v, mk, A, B, bo);
        float4 o2 = apply_vec(v2, gc2, c1, c2, c3, c4v, mk, A, B, bo);
        float4 o3 = apply_vec(v3, gc3, c1, c2, c3, c4v, mk, A, B, bo);
        __stcs(&yp[(size_t)r * D4], o0);
        __stcs(&yp[(size_t)(r + 1) * D4], o1);
        __stcs(&yp[(size_t)(r + 2) * D4], o2);
        __stcs(&yp[(size_t)(r + 3) * D4], o3);
    }
    for (; r < r_end; r++) {
        float gc0 = g_gc[r];
        float4 v0 = xp[(size_t)r * D4];
        __stcs(&yp[(size_t)r * D4], apply_vec(v0, gc0, c1, c2, c3, c4v, mk, A, B, bo));
    }
}

// ---------------- launch ----------------
extern "C" void kernel_launch(void* const* d_in, const int* in_sizes, int n_in,
                              void* d_out, int out_size)
{
    (void)n_in; (void)out_size;
    const float* x             = (const float*)d_in[0];
    const float* log_tau       = (const float*)d_in[2];
    const float* log_beta_up   = (const float*)d_in[3];
    const float* log_beta_dn   = (const float*)d_in[4];
    const float* log_gamma     = (const float*)d_in[5];
    const float* log_beta_out  = (const float*)d_in[6];
    const float* log_gamma_out = (const float*)d_in[7];
    const float* ema_mean      = (const float*)d_in[9];
    const float* ema_sq        = (const float*)d_in[10];
    const float* ema_out_mean  = (const float*)d_in[11];
    const float* ema_out_sq    = (const float*)d_in[12];
    const float* ema_out_dir   = (const float*)d_in[13];
    const int*   kptr          = (const int*)d_in[14];

    int rows = in_sizes[0] / D; // 8192 for (4, 2048, 4096)

    prep_kernel<<<1, 256>>>(ema_mean, ema_sq, ema_out_mean, ema_out_sq, ema_out_dir,
                            log_tau, log_beta_up, log_beta_dn, log_gamma,
                            log_beta_out, log_gamma_out);

    dim3 ng(4, (rows + 63) / 64);
    pass1_kernel<<<ng, 256>>>((const float4*)x, rows);

    mask_kernel<<<256, 512>>>(kptr, rows);

    int rpb = 8;
    dim3 ag(4, (rows + rpb - 1) / rpb);
    apply2_kernel<<<ag, 256>>>((const float4*)x, (float4*)d_out, rows, rpb);
}

// round 10
// speedup vs baseline: 1.6088x; 1.2628x over previous
#include <cuda_runtime.h>
#include <math.h>

#define D 4096
#define D4 1024
#define MAXR 16384
#define EPSF 1e-5f
#define EPS_VARF 1e-4f
#define PREP_BLOCKS 17

// ---------------- device scratch (static; no allocations) ----------------
__device__ __align__(16) float  g_ain[D];    // 1/(sqrt(var_in)+eps)
__device__ __align__(16) float  g_bin[D];    // -mean_in * ain
__device__ __align__(16) float  g_aout[D];   // 1/(sqrt(var_out)+eps)
__device__ __align__(16) float  g_bout[D];   // -mean_out * aout
__device__ __align__(16) float  g_mask[D];
__device__ __align__(16) double g_novel[D];
__device__ __align__(16) float  g_rows2[MAXR];
__device__ __align__(16) float  g_rowsd[MAXR];
__device__ __align__(16) float  g_gc[MAXR];
__device__ float g_scal[6]; // tau, A=(bu+bd)/2, B=(bu-bd)/2, gamma, beta_out, gamma_out
__device__ float g_invn;    // 1/||ema_out_dir||

// ---------------- fast math helpers ----------------
__device__ __forceinline__ float tanh_fast(float x) {
    float y;
    asm("tanh.approx.f32 %0, %1;" : "=f"(y) : "f"(x));
    return y;
}

__device__ __forceinline__ float gelu_f(float x) {
    float x2 = x * x;
    float arg = x * fmaf(0.035677408136300125f, x2, 0.7978845608028654f);
    float t = tanh_fast(arg);
    float h = 0.5f * x;
    return fmaf(h, t, h);
}

// ---------------- prep (parallel): block 0 = norm+scalars; blocks 1..16 = channel consts ----------------
__global__ void __launch_bounds__(256) prep_kernel(
    const float* __restrict__ ema_mean,
    const float* __restrict__ ema_sq,
    const float* __restrict__ ema_out_mean,
    const float* __restrict__ ema_out_sq,
    const float* __restrict__ ema_out_dir,
    const float* __restrict__ log_tau,
    const float* __restrict__ log_beta_up,
    const float* __restrict__ log_beta_dn,
    const float* __restrict__ log_gamma,
    const float* __restrict__ log_beta_out,
    const float* __restrict__ log_gamma_out)
{
    int b = blockIdx.x;
    int t = threadIdx.x;

    // zero accumulators, spread across all blocks
    for (int i = b * 256 + t; i < MAXR; i += PREP_BLOCKS * 256) {
        g_rows2[i] = 0.f; g_rowsd[i] = 0.f;
    }
    for (int i = b * 256 + t; i < D; i += PREP_BLOCKS * 256) g_novel[i] = 0.0;

    if (b == 0) {
        __shared__ float red[8];
        float s = 0.f;
        for (int c = t; c < D; c += 256) { float v = ema_out_dir[c]; s += v * v; }
        #pragma unroll
        for (int o = 16; o > 0; o >>= 1) s += __shfl_xor_sync(0xffffffffu, s, o);
        if ((t & 31) == 0) red[t >> 5] = s;
        __syncthreads();
        if (t == 0) {
            float tot = 0.f;
            #pragma unroll
            for (int i = 0; i < 8; i++) tot += red[i];
            g_invn = 1.0f / fmaxf(sqrtf(tot), 1e-12f);
            float bu = log1pf(expf(log_beta_up[0]));
            float bd = log1pf(expf(log_beta_dn[0]));
            g_scal[0] = expf(log_tau[0]);
            g_scal[1] = 0.5f * (bu + bd);            // A
            g_scal[2] = 0.5f * (bu - bd);            // B
            g_scal[3] = log1pf(expf(log_gamma[0]));  // gamma
            g_scal[4] = log1pf(expf(log_beta_out[0]));
            g_scal[5] = log1pf(expf(log_gamma_out[0]));
        }
    } else {
        int c = (b - 1) * 256 + t;  // blocks 1..16 cover 4096 channels
        float m   = ema_mean[c];
        float var = fmaxf(ema_sq[c] - m * m, EPS_VARF);
        float ai  = 1.0f / (sqrtf(var) + EPSF);
        g_ain[c] = ai;
        g_bin[c] = -m * ai;
        float mo   = ema_out_mean[c];
        float varo = fmaxf(ema_out_sq[c] - mo * mo, EPS_VARF);
        float ao   = 1.0f / (sqrtf(varo) + EPSF);
        g_aout[c] = ao;
        g_bout[c] = -mo * ao;
    }
}

// ---------------- pass 1: per-channel novelty (fp32 in-block, fp64 across blocks) + per-row sums ----------------
// grid: (4, rows/64), block: 256. Thread owns one float4 column group across 64 rows.
__global__ void __launch_bounds__(256) pass1_kernel(const float4* __restrict__ x4,
                                                    const float4* __restrict__ dir4,
                                                    int rows)
{
    int t = threadIdx.x;
    int lane = t & 31;

    int c4 = blockIdx.x * 256 + t;
    int r0 = blockIdx.y * 64;

    const float4 ai = *(const float4*)&g_ain[c4 * 4];
    const float4 bi = *(const float4*)&g_bin[c4 * 4];
    const float4 ea = dir4[c4];   // raw (unnormalized) direction; invn folded into mask

    float n0 = 0.f, n1 = 0.f, n2 = 0.f, n3 = 0.f;  // fp32 novelty acc (64 rows)
    const float4* p = x4 + (size_t)r0 * D4 + c4;

    if (r0 + 64 <= rows) {
        for (int tile = 0; tile < 8; tile++) {
            int rb = tile * 8;
            float4 v[8];
            #pragma unroll
            for (int i = 0; i < 8; i++) v[i] = p[(size_t)(rb + i) * D4];

            float p0 = 0.f, p1 = 0.f, p2 = 0.f, p3 = 0.f;
            #pragma unroll
            for (int i = 0; i < 8; i++) {
                float z0 = fmaf(v[i].x, ai.x, bi.x);
                float z1 = fmaf(v[i].y, ai.y, bi.y);
                float z2 = fmaf(v[i].z, ai.z, bi.z);
                float z3 = fmaf(v[i].w, ai.w, bi.w);
                p0 += fabsf(z0); p1 += fabsf(z1); p2 += fabsf(z2); p3 += fabsf(z3);
                float o0 = gelu_f(v[i].x), o1 = gelu_f(v[i].y);
                float o2 = gelu_f(v[i].z), o3 = gelu_f(v[i].w);
                float s2 = fmaf(o0, o0, fmaf(o1, o1, fmaf(o2, o2, o3 * o3)));
                float sd = fmaf(o0, ea.x, fmaf(o1, ea.y, fmaf(o2, ea.z, o3 * ea.w)));
                #pragma unroll
                for (int o = 16; o > 0; o >>= 1) {
                    float s2o = __shfl_xor_sync(0xffffffffu, s2, o);
                    float sdo = __shfl_xor_sync(0xffffffffu, sd, o);
                    s2 += s2o;
                    sd += sdo;
                }
                if (lane == 0) {
                    atomicAdd(&g_rows2[r0 + rb + i], s2);
                    atomicAdd(&g_rowsd[r0 + rb + i], sd);
                }
            }
            n0 += p0; n1 += p1; n2 += p2; n3 += p3;
        }
    } else {
        int nr = rows - r0; if (nr < 0) nr = 0;
        for (int r = 0; r < nr; r++) {
            float4 v = p[(size_t)r * D4];
            float z0 = fmaf(v.x, ai.x, bi.x);
            float z1 = fmaf(v.y, ai.y, bi.y);
            float z2 = fmaf(v.z, ai.z, bi.z);
            float z3 = fmaf(v.w, ai.w, bi.w);
            n0 += fabsf(z0); n1 += fabsf(z1); n2 += fabsf(z2); n3 += fabsf(z3);
            float o0 = gelu_f(v.x), o1 = gelu_f(v.y);
            float o2 = gelu_f(v.z), o3 = gelu_f(v.w);
            float s2 = fmaf(o0, o0, fmaf(o1, o1, fmaf(o2, o2, o3 * o3)));
            float sd = fmaf(o0, ea.x, fmaf(o1, ea.y, fmaf(o2, ea.z, o3 * ea.w)));
            #pragma unroll
            for (int o = 16; o > 0; o >>= 1) {
                float s2o = __shfl_xor_sync(0xffffffffu, s2, o);
                float sdo = __shfl_xor_sync(0xffffffffu, sd, o);
                s2 += s2o;
                sd += sdo;
            }
            if (lane == 0) {
                atomicAdd(&g_rows2[r0 + r], s2);
                atomicAdd(&g_rowsd[r0 + r], sd);
            }
        }
    }

    // one fp64 convert + atomic per channel per block (cross-block sums stay fp64)
    atomicAdd(&g_novel[c4 * 4 + 0], (double)n0);
    atomicAdd(&g_novel[c4 * 4 + 1], (double)n1);
    atomicAdd(&g_novel[c4 * 4 + 2], (double)n2);
    atomicAdd(&g_novel[c4 * 4 + 3], (double)n3);
}

// ---------------- top-k hard mask (exact rank, int64 keys) + gate_cos finalize ----------------
__global__ void __launch_bounds__(512) mask_kernel(const int* __restrict__ kptr, int rows)
{
    __shared__ long long s[D];
    int t = threadIdx.x;
    for (int c = t; c < D; c += 512) s[c] = __double_as_longlong(g_novel[c]);

    int rowid = blockIdx.x * 512 + t;
    if (rowid < rows) {
        float s2v = g_rows2[rowid];
        float sdv = g_rowsd[rowid] * g_invn;   // fold direction normalization here
        float nrm = fmaxf(sqrtf(s2v), 1e-12f);
        float cs  = fminf(fmaxf(sdv / nrm, -1.0f), 1.0f);
        g_gc[rowid] = expf(-g_scal[0] * cs);
    }
    __syncthreads();

    int k = kptr[0];
    if (k < 1 || k > D) {
        float kf = __int_as_float(k);
        if (kf >= 1.0f && kf <= (float)D) k = (int)kf;
        else if (k < 1) k = 1;
        else k = D;
    }

    int w = t >> 5, lane = t & 31;
    int d = blockIdx.x * 16 + w;       // 256*16 = 4096 channels
    long long sd = s[d];
    int cnt = 0;
    #pragma unroll 4
    for (int jj = 0; jj < D / 32; jj++) {
        int j = jj * 32 + lane;
        long long v = s[j];
        bool p = (v > sd) || (v == sd && j < d);
        cnt += __popc(__ballot_sync(0xffffffffu, p));
    }
    if (lane == 0) g_mask[d] = (cnt < k) ? 1.0f : 0.0f;
}

// ---------------- pass 2: streaming apply, reversed rows, 4+4 software pipeline ----------------
__device__ __forceinline__ float apply_one(float x, float gc,
                                           float c1, float c2, float c3, float c4,
                                           float mk, float A, float B, float bo)
{
    float o = gelu_f(x);
    float t1 = tanh_fast(fmaf(x, c1, c2));
    float gin = fmaf(B, fabsf(t1), fmaf(A, t1, 1.0f));
    gin = fminf(fmaxf(gin, 0.05f), 8.0f);
    float t2 = tanh_fast(fmaf(o, c3, c4));
    float gout = fmaf(bo, t2, 1.0f);
    gout = fminf(fmaxf(gout, 0.1f), 5.0f);
    float g = gin * gout * gc;
    return o * fmaf(mk, g - 1.0f, 1.0f);
}

__device__ __forceinline__ float4 apply_vec(float4 v, float gc,
                                            const float4& c1, const float4& c2,
                                            const float4& c3, const float4& c4,
                                            const float4& mk,
                                            float A, float B, float bo)
{
    float4 r;
    r.x = apply_one(v.x, gc, c1.x, c2.x, c3.x, c4.x, mk.x, A, B, bo);
    r.y = apply_one(v.y, gc, c1.y, c2.y, c3.y, c4.y, mk.y, A, B, bo);
    r.z = apply_one(v.z, gc, c1.z, c2.z, c3.z, c4.z, mk.z, A, B, bo);
    r.w = apply_one(v.w, gc, c1.w, c2.w, c3.w, c4.w, mk.w, A, B, bo);
    return r;
}

// grid (4, ceil(rows/8)), block 256, reversed row mapping (L2-LIFO after pass1).
// Fast path (full 8-row block, 4-aligned): all 8 loads issued before first
// compute -> MLP 8; two 4-row halves pipeline compute against loads.
__global__ void __launch_bounds__(256) apply2_kernel(const float4* __restrict__ x4,
                                                     float4* __restrict__ y4,
                                                     int rows)
{
    int t = threadIdx.x;
    int c4 = blockIdx.x * 256 + t;

    const float gm = g_scal[3], go = g_scal[5];
    const float A = g_scal[1], B = g_scal[2], bo = g_scal[4];

    float4 c1 = *(const float4*)&g_ain[c4 * 4];
    float4 c2 = *(const float4*)&g_bin[c4 * 4];
    float4 c3 = *(const float4*)&g_aout[c4 * 4];
    float4 c4v = *(const float4*)&g_bout[c4 * 4];
    const float4 mk = *(const float4*)&g_mask[c4 * 4];
    c1.x *= gm; c1.y *= gm; c1.z *= gm; c1.w *= gm;
    c2.x *= gm; c2.y *= gm; c2.z *= gm; c2.w *= gm;
    c3.x *= go; c3.y *= go; c3.z *= go; c3.w *= go;
    c4v.x *= go; c4v.y *= go; c4v.z *= go; c4v.w *= go;

    int r_end = rows - blockIdx.y * 8;
    int r_begin = r_end - 8; if (r_begin < 0) r_begin = 0;

    const float4* xp = x4 + c4;
    float4* yp = y4 + c4;

    if (r_end - r_begin == 8 && (r_begin & 3) == 0) {
        int r = r_begin;
        float4 gca = *(const float4*)&g_gc[r];
        float4 gcb = *(const float4*)&g_gc[r + 4];
        float4 v[4], w[4];
        #pragma unroll
        for (int i = 0; i < 4; i++) v[i] = xp[(size_t)(r + i) * D4];
        #pragma unroll
        for (int i = 0; i < 4; i++) w[i] = xp[(size_t)(r + 4 + i) * D4];

        float4 o0 = apply_vec(v[0], gca.x, c1, c2, c3, c4v, mk, A, B, bo);
        float4 o1 = apply_vec(v[1], gca.y, c1, c2, c3, c4v, mk, A, B, bo);
        float4 o2 = apply_vec(v[2], gca.z, c1, c2, c3, c4v, mk, A, B, bo);
        float4 o3 = apply_vec(v[3], gca.w, c1, c2, c3, c4v, mk, A, B, bo);
        __stcs(&yp[(size_t)(r + 0) * D4], o0);
        __stcs(&yp[(size_t)(r + 1) * D4], o1);
        __stcs(&yp[(size_t)(r + 2) * D4], o2);
        __stcs(&yp[(size_t)(r + 3) * D4], o3);

        float4 q0 = apply_vec(w[0], gcb.x, c1, c2, c3, c4v, mk, A, B, bo);
        float4 q1 = apply_vec(w[1], gcb.y, c1, c2, c3, c4v, mk, A, B, bo);
        float4 q2 = apply_vec(w[2], gcb.z, c1, c2, c3, c4v, mk, A, B, bo);
        float4 q3 = apply_vec(w[3], gcb.w, c1, c2, c3, c4v, mk, A, B, bo);
        __stcs(&yp[(size_t)(r + 4) * D4], q0);
        __stcs(&yp[(size_t)(r + 5) * D4], q1);
        __stcs(&yp[(size_t)(r + 6) * D4], q2);
        __stcs(&yp[(size_t)(r + 7) * D4], q3);
    } else {
        for (int r = r_begin; r < r_end; r++) {
            float gc0 = g_gc[r];
            float4 v0 = xp[(size_t)r * D4];
            __stcs(&yp[(size_t)r * D4], apply_vec(v0, gc0, c1, c2, c3, c4v, mk, A, B, bo));
        }
    }
}

// ---------------- launch ----------------
extern "C" void kernel_launch(void* const* d_in, const int* in_sizes, int n_in,
                              void* d_out, int out_size)
{
    (void)n_in; (void)out_size;
    const float* x             = (const float*)d_in[0];
    const float* log_tau       = (const float*)d_in[2];
    const float* log_beta_up   = (const float*)d_in[3];
    const float* log_beta_dn   = (const float*)d_in[4];
    const float* log_gamma     = (const float*)d_in[5];
    const float* log_beta_out  = (const float*)d_in[6];
    const float* log_gamma_out = (const float*)d_in[7];
    const float* ema_mean      = (const float*)d_in[9];
    const float* ema_sq        = (const float*)d_in[10];
    const float* ema_out_mean  = (const float*)d_in[11];
    const float* ema_out_sq    = (const float*)d_in[12];
    const float* ema_out_dir   = (const float*)d_in[13];
    const int*   kptr          = (const int*)d_in[14];

    int rows = in_sizes[0] / D; // 8192 for (4, 2048, 4096)

    prep_kernel<<<PREP_BLOCKS, 256>>>(ema_mean, ema_sq, ema_out_mean, ema_out_sq, ema_out_dir,
                                      log_tau, log_beta_up, log_beta_dn, log_gamma,
                                      log_beta_out, log_gamma_out);

    dim3 ng(4, (rows + 63) / 64);
    pass1_kernel<<<ng, 256>>>((const float4*)x, (const float4*)ema_out_dir, rows);

    mask_kernel<<<256, 512>>>(kptr, rows);

    dim3 ag(4, (rows + 7) / 8);
    apply2_kernel<<<ag, 256>>>((const float4*)x, (float4*)d_out, rows);
}